// round 2
// baseline (speedup 1.0000x reference)
#include <cuda_runtime.h>

// Problem constants (from reference)
#define D_H      512
#define D_MODEL  2048
#define BB       4
#define TT       4096
#define NKC      8                 // K-split chunks for the 2048-deep GEMVs
#define KC       (D_MODEL / NKC)   // 256

// Scratch: __device__ globals (no allocation allowed)
__device__ __align__(16) float g_MEM[BB * D_MODEL];             // mem = zH @ W_mem
__device__ __align__(16) float g_PV [NKC * BB * D_MODEL];       // partials of V = mem @ W_v
__device__ __align__(16) float g_POV[NKC * BB * D_MODEL];       // partials of ov = V @ W_o

// ---------------------------------------------------------------------------
// Kernel 1: mem[b, o] = sum_i zH[b, i] * W_mem[i, o]    (K = 512, no split)
// grid = 8 blocks x 256 threads; o = blockIdx.x*256 + tid
// ---------------------------------------------------------------------------
__global__ void k_mem(const float* __restrict__ zH, const float* __restrict__ Wm) {
    __shared__ float xs[BB * D_H];
    const int tid = threadIdx.x;
    for (int i = tid; i < BB * D_H; i += 256) xs[i] = zH[i];
    __syncthreads();

    const int o = blockIdx.x * 256 + tid;
    float a0 = 0.f, a1 = 0.f, a2 = 0.f, a3 = 0.f;
    const float* W = Wm + o;
    #pragma unroll 4
    for (int i = 0; i < D_H; ++i) {
        float w = W[(size_t)i * D_MODEL];
        a0 += xs[0 * D_H + i] * w;
        a1 += xs[1 * D_H + i] * w;
        a2 += xs[2 * D_H + i] * w;
        a3 += xs[3 * D_H + i] * w;
    }
    g_MEM[0 * D_MODEL + o] = a0;
    g_MEM[1 * D_MODEL + o] = a1;
    g_MEM[2 * D_MODEL + o] = a2;
    g_MEM[3 * D_MODEL + o] = a3;
}

// ---------------------------------------------------------------------------
// Kernel 2: V partials.  PV[kc][b][o] = sum_{i in chunk kc} mem[b,i]*W_v[i,o]
// grid = (8 out-chunks, NKC k-chunks) x 256 threads
// ---------------------------------------------------------------------------
__global__ void k_v(const float* __restrict__ Wv) {
    __shared__ float xs[BB][KC];
    const int tid = threadIdx.x;
    const int kc  = blockIdx.y;
    for (int i = tid; i < BB * KC; i += 256) {
        int b = i / KC, j = i % KC;
        xs[b][j] = g_MEM[b * D_MODEL + kc * KC + j];
    }
    __syncthreads();

    const int o = blockIdx.x * 256 + tid;
    float a0 = 0.f, a1 = 0.f, a2 = 0.f, a3 = 0.f;
    const float* W = Wv + (size_t)kc * KC * D_MODEL + o;
    #pragma unroll 4
    for (int j = 0; j < KC; ++j) {
        float w = W[(size_t)j * D_MODEL];
        a0 += xs[0][j] * w;
        a1 += xs[1][j] * w;
        a2 += xs[2][j] * w;
        a3 += xs[3][j] * w;
    }
    float* P = g_PV + (size_t)kc * BB * D_MODEL;
    P[0 * D_MODEL + o] = a0;
    P[1 * D_MODEL + o] = a1;
    P[2 * D_MODEL + o] = a2;
    P[3 * D_MODEL + o] = a3;
}

// ---------------------------------------------------------------------------
// Kernel 3: ov partials.  Reduces V partials into smem, then GEMV with W_o.
// POV[kc][b][o] = sum_{i in chunk kc} V[b,i]*W_o[i,o]
// ---------------------------------------------------------------------------
__global__ void k_ov(const float* __restrict__ Wo) {
    __shared__ float xs[BB][KC];
    const int tid = threadIdx.x;
    const int kc  = blockIdx.y;
    for (int i = tid; i < BB * KC; i += 256) {
        int b = i / KC, j = i % KC;
        float s = 0.f;
        #pragma unroll
        for (int p = 0; p < NKC; ++p)
            s += g_PV[((size_t)p * BB + b) * D_MODEL + kc * KC + j];
        xs[b][j] = s;
    }
    __syncthreads();

    const int o = blockIdx.x * 256 + tid;
    float a0 = 0.f, a1 = 0.f, a2 = 0.f, a3 = 0.f;
    const float* W = Wo + (size_t)kc * KC * D_MODEL + o;
    #pragma unroll 4
    for (int j = 0; j < KC; ++j) {
        float w = W[(size_t)j * D_MODEL];
        a0 += xs[0][j] * w;
        a1 += xs[1][j] * w;
        a2 += xs[2][j] * w;
        a3 += xs[3][j] * w;
    }
    float* P = g_POV + (size_t)kc * BB * D_MODEL;
    P[0 * D_MODEL + o] = a0;
    P[1 * D_MODEL + o] = a1;
    P[2 * D_MODEL + o] = a2;
    P[3 * D_MODEL + o] = a3;
}

// ---------------------------------------------------------------------------
// Kernel 4: out[b,t,:] = lh[b,t,:] + sigmoid(gate) * ov[b,:]
// grid = (TCHUNKS=64, B=4) x 512 threads. Each thread owns one float4 column
// of the row (D_MODEL/4 = 512), reduces its ov slice once into a register
// (folding the POV reduction in), then streams T/64 = 64 rows.
// ---------------------------------------------------------------------------
#define TCHUNKS 64
#define ROWS_PER_BLOCK (TT / TCHUNKS)   // 64

__global__ void __launch_bounds__(512) k_main(const float* __restrict__ lh,
                                              const float* __restrict__ gate,
                                              float* __restrict__ out) {
    const int b  = blockIdx.y;
    const int d4 = threadIdx.x;   // 0..511 float4 column

    // Reduce POV partials for this (b, d4): 8 L2-hot float4 loads.
    float4 ov = make_float4(0.f, 0.f, 0.f, 0.f);
    const float4* P = reinterpret_cast<const float4*>(g_POV);
    #pragma unroll
    for (int p = 0; p < NKC; ++p) {
        float4 v = P[((size_t)p * BB + b) * (D_MODEL / 4) + d4];
        ov.x += v.x; ov.y += v.y; ov.z += v.z; ov.w += v.w;
    }
    const float g  = *gate;
    const float sg = 1.f / (1.f + expf(-g));
    ov.x *= sg; ov.y *= sg; ov.z *= sg; ov.w *= sg;

    const int t0 = blockIdx.x * ROWS_PER_BLOCK;
    const float4* LH = reinterpret_cast<const float4*>(lh);
    float4*       O  = reinterpret_cast<float4*>(out);
    size_t idx = ((size_t)b * TT + t0) * (D_MODEL / 4) + d4;

    #pragma unroll 4
    for (int tt = 0; tt < ROWS_PER_BLOCK; ++tt) {
        float4 x = LH[idx];
        x.x += ov.x; x.y += ov.y; x.z += ov.z; x.w += ov.w;
        O[idx] = x;
        idx += (D_MODEL / 4);
    }
}

// ---------------------------------------------------------------------------
// Input order (metadata): 0 last_hidden, 1 zH, 2 W_mem, 3 W_q, 4 W_k,
//                         5 W_v, 6 W_o, 7 gate.  Output: float32 B*T*D.
// ---------------------------------------------------------------------------
extern "C" void kernel_launch(void* const* d_in, const int* in_sizes, int n_in,
                              void* d_out, int out_size) {
    const float* lh   = (const float*)d_in[0];
    const float* zH   = (const float*)d_in[1];
    const float* Wm   = (const float*)d_in[2];
    const float* Wv   = (const float*)d_in[5];
    const float* Wo   = (const float*)d_in[6];
    const float* gate = (const float*)d_in[7];
    float* out = (float*)d_out;

    k_mem<<<8, 256>>>(zH, Wm);
    k_v  <<<dim3(8, NKC), 256>>>(Wv);
    k_ov <<<dim3(8, NKC), 256>>>(Wo);
    k_main<<<dim3(TCHUNKS, BB), 512>>>(lh, gate, out);
}

// round 3
// speedup vs baseline: 2.2786x; 2.2786x over previous
#include <cuda_runtime.h>

// Problem constants (from reference)
#define D_H      512
#define D_MODEL  2048
#define BB       4
#define TT       4096
#define O4       (D_MODEL / 4)     // 512 float4 outputs per row

// K-split factors
#define NK_M     16                // k_mem: 512/16 = 32 rows per chunk
#define KC_M     (D_H / NK_M)      // 32
#define NK_V     32                // k_v / k_ov: 2048/32 = 64 rows per chunk
#define KC_V     (D_MODEL / NK_V)  // 64

// Scratch (__device__ globals; no allocation allowed)
__device__ __align__(16) float g_PM [NK_M * BB * D_MODEL];   // 512 KB: partials of mem = zH @ W_mem
__device__ __align__(16) float g_PV [NK_V * BB * D_MODEL];   // 1 MB:   partials of V   = mem @ W_v
__device__ __align__(16) float g_POV[NK_V * BB * D_MODEL];   // 1 MB:   partials of ov  = V @ W_o
__device__ __align__(16) float g_OV [BB * D_MODEL];          // 32 KB:  sigmoid(gate) * ov

// ---------------------------------------------------------------------------
// Kernel 1: mem partials.  PM[kc][b][o] = sum_{i in chunk} zH[b,i]*W_mem[i,o]
// grid = (4 o-chunks, 16 k-chunks) x 128 threads; float4 weight loads.
// ---------------------------------------------------------------------------
__global__ void __launch_bounds__(128) k_mem(const float* __restrict__ zH,
                                             const float* __restrict__ Wm) {
    __shared__ float xs[BB][KC_M];
    const int tid = threadIdx.x;
    const int kc  = blockIdx.y;
    // 4*32 = 128 entries, one per thread
    {
        int b = tid / KC_M, j = tid % KC_M;
        xs[b][j] = zH[b * D_H + kc * KC_M + j];
    }
    __syncthreads();

    const int o4 = blockIdx.x * 128 + tid;
    const float4* W4 = reinterpret_cast<const float4*>(Wm);
    float4 a0 = {0,0,0,0}, a1 = {0,0,0,0}, a2 = {0,0,0,0}, a3 = {0,0,0,0};
    #pragma unroll 16
    for (int j = 0; j < KC_M; ++j) {
        float4 w = W4[(size_t)(kc * KC_M + j) * O4 + o4];
        float x0 = xs[0][j], x1 = xs[1][j], x2 = xs[2][j], x3 = xs[3][j];
        a0.x += x0*w.x; a0.y += x0*w.y; a0.z += x0*w.z; a0.w += x0*w.w;
        a1.x += x1*w.x; a1.y += x1*w.y; a1.z += x1*w.z; a1.w += x1*w.w;
        a2.x += x2*w.x; a2.y += x2*w.y; a2.z += x2*w.z; a2.w += x2*w.w;
        a3.x += x3*w.x; a3.y += x3*w.y; a3.z += x3*w.z; a3.w += x3*w.w;
    }
    float4* P4 = reinterpret_cast<float4*>(g_PM);
    P4[((size_t)kc * BB + 0) * O4 + o4] = a0;
    P4[((size_t)kc * BB + 1) * O4 + o4] = a1;
    P4[((size_t)kc * BB + 2) * O4 + o4] = a2;
    P4[((size_t)kc * BB + 3) * O4 + o4] = a3;
}

// ---------------------------------------------------------------------------
// Kernel 2: V partials. Folds PM reduction into smem stage (L2-hot, 4 KB).
// PV[kc][b][o] = sum_{i in chunk} mem[b,i]*W_v[i,o]
// grid = (4 o-chunks, 32 k-chunks) x 128 threads.
// ---------------------------------------------------------------------------
__global__ void __launch_bounds__(128) k_v(const float* __restrict__ Wv) {
    __shared__ float xs[BB][KC_V];
    const int tid = threadIdx.x;
    const int kc  = blockIdx.y;
    for (int i = tid; i < BB * KC_V; i += 128) {
        int b = i / KC_V, j = i % KC_V;
        int col = kc * KC_V + j;
        float s = 0.f;
        #pragma unroll
        for (int p = 0; p < NK_M; ++p)
            s += g_PM[((size_t)p * BB + b) * D_MODEL + col];
        xs[b][j] = s;
    }
    __syncthreads();

    const int o4 = blockIdx.x * 128 + tid;
    const float4* W4 = reinterpret_cast<const float4*>(Wv);
    float4 a0 = {0,0,0,0}, a1 = {0,0,0,0}, a2 = {0,0,0,0}, a3 = {0,0,0,0};
    #pragma unroll 16
    for (int j = 0; j < KC_V; ++j) {
        float4 w = W4[(size_t)(kc * KC_V + j) * O4 + o4];
        float x0 = xs[0][j], x1 = xs[1][j], x2 = xs[2][j], x3 = xs[3][j];
        a0.x += x0*w.x; a0.y += x0*w.y; a0.z += x0*w.z; a0.w += x0*w.w;
        a1.x += x1*w.x; a1.y += x1*w.y; a1.z += x1*w.z; a1.w += x1*w.w;
        a2.x += x2*w.x; a2.y += x2*w.y; a2.z += x2*w.z; a2.w += x2*w.w;
        a3.x += x3*w.x; a3.y += x3*w.y; a3.z += x3*w.z; a3.w += x3*w.w;
    }
    float4* P4 = reinterpret_cast<float4*>(g_PV);
    P4[((size_t)kc * BB + 0) * O4 + o4] = a0;
    P4[((size_t)kc * BB + 1) * O4 + o4] = a1;
    P4[((size_t)kc * BB + 2) * O4 + o4] = a2;
    P4[((size_t)kc * BB + 3) * O4 + o4] = a3;
}

// ---------------------------------------------------------------------------
// Kernel 3: ov partials. Folds PV reduction into smem stage (32 KB L2-hot).
// POV[kc][b][o] = sum_{i in chunk} V[b,i]*W_o[i,o]
// ---------------------------------------------------------------------------
__global__ void __launch_bounds__(128) k_ov(const float* __restrict__ Wo) {
    __shared__ float xs[BB][KC_V];
    const int tid = threadIdx.x;
    const int kc  = blockIdx.y;
    for (int i = tid; i < BB * KC_V; i += 128) {
        int b = i / KC_V, j = i % KC_V;
        int col = kc * KC_V + j;
        float s = 0.f;
        #pragma unroll
        for (int p = 0; p < NK_V; ++p)
            s += g_PV[((size_t)p * BB + b) * D_MODEL + col];
        xs[b][j] = s;
    }
    __syncthreads();

    const int o4 = blockIdx.x * 128 + tid;
    const float4* W4 = reinterpret_cast<const float4*>(Wo);
    float4 a0 = {0,0,0,0}, a1 = {0,0,0,0}, a2 = {0,0,0,0}, a3 = {0,0,0,0};
    #pragma unroll 16
    for (int j = 0; j < KC_V; ++j) {
        float4 w = W4[(size_t)(kc * KC_V + j) * O4 + o4];
        float x0 = xs[0][j], x1 = xs[1][j], x2 = xs[2][j], x3 = xs[3][j];
        a0.x += x0*w.x; a0.y += x0*w.y; a0.z += x0*w.z; a0.w += x0*w.w;
        a1.x += x1*w.x; a1.y += x1*w.y; a1.z += x1*w.z; a1.w += x1*w.w;
        a2.x += x2*w.x; a2.y += x2*w.y; a2.z += x2*w.z; a2.w += x2*w.w;
        a3.x += x3*w.x; a3.y += x3*w.y; a3.z += x3*w.z; a3.w += x3*w.w;
    }
    float4* P4 = reinterpret_cast<float4*>(g_POV);
    P4[((size_t)kc * BB + 0) * O4 + o4] = a0;
    P4[((size_t)kc * BB + 1) * O4 + o4] = a1;
    P4[((size_t)kc * BB + 2) * O4 + o4] = a2;
    P4[((size_t)kc * BB + 3) * O4 + o4] = a3;
}

// ---------------------------------------------------------------------------
// Kernel 4: g_OV[b][o] = sigmoid(gate) * sum_p POV[p][b][o]   (8192 outputs)
// ---------------------------------------------------------------------------
__global__ void __launch_bounds__(512) k_red_ov(const float* __restrict__ gate) {
    const int e = blockIdx.x * 512 + threadIdx.x;   // [0, 8192)
    const int b = e >> 11;
    const int o = e & (D_MODEL - 1);
    float s = 0.f;
    #pragma unroll
    for (int p = 0; p < NK_V; ++p)
        s += g_POV[((size_t)p * BB + b) * D_MODEL + o];
    const float g = *gate;
    g_OV[e] = s * (1.f / (1.f + expf(-g)));
}

// ---------------------------------------------------------------------------
// Kernel 5: out[b,t,:] = lh[b,t,:] + g_OV[b,:]
// grid = (128 t-chunks, 4 batches) x 512 threads; 32 rows/block; 2 blocks/SM.
// ---------------------------------------------------------------------------
#define TCHUNKS 128
#define ROWS_PER_BLOCK (TT / TCHUNKS)   // 32

__global__ void __launch_bounds__(512) k_main(const float* __restrict__ lh,
                                              float* __restrict__ out) {
    const int b  = blockIdx.y;
    const int d4 = threadIdx.x;   // 0..511 float4 column

    const float4 ov = reinterpret_cast<const float4*>(g_OV)[b * O4 + d4];

    const int t0 = blockIdx.x * ROWS_PER_BLOCK;
    const float4* LH = reinterpret_cast<const float4*>(lh);
    float4*       O  = reinterpret_cast<float4*>(out);
    size_t idx = ((size_t)b * TT + t0) * O4 + d4;

    #pragma unroll 8
    for (int tt = 0; tt < ROWS_PER_BLOCK; ++tt) {
        float4 x = LH[idx];
        x.x += ov.x; x.y += ov.y; x.z += ov.z; x.w += ov.w;
        O[idx] = x;
        idx += O4;
    }
}

// ---------------------------------------------------------------------------
// Input order: 0 last_hidden, 1 zH, 2 W_mem, 3 W_q, 4 W_k, 5 W_v, 6 W_o, 7 gate
// ---------------------------------------------------------------------------
extern "C" void kernel_launch(void* const* d_in, const int* in_sizes, int n_in,
                              void* d_out, int out_size) {
    const float* lh   = (const float*)d_in[0];
    const float* zH   = (const float*)d_in[1];
    const float* Wm   = (const float*)d_in[2];
    const float* Wv   = (const float*)d_in[5];
    const float* Wo   = (const float*)d_in[6];
    const float* gate = (const float*)d_in[7];
    float* out = (float*)d_out;

    k_mem   <<<dim3(4, NK_M), 128>>>(zH, Wm);
    k_v     <<<dim3(4, NK_V), 128>>>(Wv);
    k_ov    <<<dim3(4, NK_V), 128>>>(Wo);
    k_red_ov<<<16, 512>>>(gate);
    k_main  <<<dim3(TCHUNKS, BB), 512>>>(lh, out);
}